// round 3
// baseline (speedup 1.0000x reference)
#include <cuda_runtime.h>
#include <cstdint>

#define N_TOK 8192
#define D     512
#define E     16
#define H     2048
#define CAP   1024
#define ROWS_PER_E 2048   // b * CAP

// ---------------- scratch (static device globals; no allocation) ----------------
// Declared as float4 arrays so 128-bit accesses are guaranteed aligned.
__device__ float4 g_ein4 [(size_t)E * ROWS_PER_E * (D / 4)];   // expert inputs  [e][b*c][d]
__device__ float4 g_hid4 [(size_t)E * ROWS_PER_E * (H / 4)];   // hidden         [e][b*c][h]
__device__ float4 g_eout4[(size_t)E * ROWS_PER_E * (D / 4)];   // expert outputs [e][b*c][d]
__device__ int   g_i1[N_TOK], g_i2[N_TOK];
__device__ int   g_s1[N_TOK], g_s2[N_TOK];
__device__ float g_g1[N_TOK], g_g2[N_TOK];
__device__ int   g_used[E * 2];                                // used rows per (e, b)

// ---------------- 1) gating: logits -> softmax -> top2 ----------------
__global__ void gating_kernel(const float* __restrict__ x, const float* __restrict__ wg)
{
    __shared__ float wgs[E][D];
    const int tid = threadIdx.x;
    for (int i = tid; i < D * E; i += blockDim.x) {
        // wg is [d][e] row-major; store transposed for conflict-free reads
        wgs[i & (E - 1)][i >> 4] = wg[i];
    }
    __syncthreads();

    const int lane = tid & 31, warp = tid >> 5;
    const int tok = blockIdx.x * (blockDim.x >> 5) + warp;
    const float* xp = x + (size_t)tok * D;

    float acc[E];
#pragma unroll
    for (int e = 0; e < E; e++) acc[e] = 0.f;
    for (int d = lane; d < D; d += 32) {
        const float xv = xp[d];
#pragma unroll
        for (int e = 0; e < E; e++) acc[e] = fmaf(xv, wgs[e][d], acc[e]);
    }
#pragma unroll
    for (int off = 16; off; off >>= 1)
#pragma unroll
        for (int e = 0; e < E; e++) acc[e] += __shfl_xor_sync(0xffffffffu, acc[e], off);

    if (lane == 0) {
        float m = acc[0];
#pragma unroll
        for (int e = 1; e < E; e++) m = fmaxf(m, acc[e]);
        float p[E]; float s = 0.f;
#pragma unroll
        for (int e = 0; e < E; e++) { p[e] = expf(acc[e] - m); s += p[e]; }
        int i1 = 0; float v1 = p[0];
#pragma unroll
        for (int e = 1; e < E; e++) if (p[e] > v1) { v1 = p[e]; i1 = e; }   // first-max tie-break
        int i2 = -1; float v2 = -1.f;
#pragma unroll
        for (int e = 0; e < E; e++) if (e != i1 && p[e] > v2) { v2 = p[e]; i2 = e; }
        const float inv = 1.f / s;
        const float gate1 = v1 * inv, gate2 = v2 * inv;
        const float denom = gate1 + gate2 + 1e-9f;
        g_i1[tok] = i1;            g_i2[tok] = i2;
        g_g1[tok] = gate1 / denom; g_g2[tok] = gate2 / denom;
    }
}

// ---------------- 2) scheduler: per-(b,e) positions via block scan ----------------
// 1 block per batch, 512 threads, 8 tokens/thread (token order preserved).
__global__ void schedule_kernel()
{
    const int b    = blockIdx.x;
    const int t    = threadIdx.x;            // 0..511
    const int lane = t & 31, warp = t >> 5;  // 16 warps
    __shared__ int warpTot[16][E];
    __shared__ int warpPre[16][E];
    __shared__ int totS[E];
    __shared__ int baseS[E];
    const int tokBase = b * 4096 + t * 8;

    for (int phase = 0; phase < 2; phase++) {
        const int* gidx = phase ? g_i2 : g_i1;
        int eidx[8];
#pragma unroll
        for (int k = 0; k < 8; k++) eidx[k] = gidx[tokBase + k];

        int inc[E], myc[E];
#pragma unroll
        for (int e = 0; e < E; e++) inc[e] = 0;
#pragma unroll
        for (int k = 0; k < 8; k++)
#pragma unroll
            for (int e = 0; e < E; e++) inc[e] += (eidx[k] == e);
#pragma unroll
        for (int e = 0; e < E; e++) myc[e] = inc[e];

        // warp inclusive scan of the 16-vector
        for (int off = 1; off < 32; off <<= 1) {
#pragma unroll
            for (int e = 0; e < E; e++) {
                const int v = __shfl_up_sync(0xffffffffu, inc[e], off);
                if (lane >= off) inc[e] += v;
            }
        }
        if (lane == 31) {
#pragma unroll
            for (int e = 0; e < E; e++) warpTot[warp][e] = inc[e];
        }
        __syncthreads();
        // cross-warp scan: warp w handles expert w
        {
            const int v = (lane < 16) ? warpTot[lane][warp] : 0;
            int iv = v;
            for (int off = 1; off < 16; off <<= 1) {
                const int u = __shfl_up_sync(0xffffffffu, iv, off);
                if (lane >= off) iv += u;
            }
            if (lane < 16)  warpPre[lane][warp] = iv - v;
            if (lane == 15) totS[warp] = iv;
        }
        __syncthreads();

        int prefix[E];
#pragma unroll
        for (int e = 0; e < E; e++)
            prefix[e] = (phase ? baseS[e] : 0) + warpPre[warp][e] + (inc[e] - myc[e]);

        // per-token positions (select-based lookup; no local-memory spill)
#pragma unroll
        for (int k = 0; k < 8; k++) {
            int pos = 0;
#pragma unroll
            for (int j = 0; j < k; j++) pos += (eidx[j] == eidx[k]);
#pragma unroll
            for (int e = 0; e < E; e++) pos += (eidx[k] == e) ? prefix[e] : 0;
            const bool kept = pos < CAP;
            if (phase == 0) {
                g_s1[tokBase + k] = kept ? pos : -1;
                if (!kept) g_g1[tokBase + k] = 0.f;
            } else {
                g_s2[tokBase + k] = kept ? pos : -1;
                if (!kept) g_g2[tokBase + k] = 0.f;
            }
        }

        if (phase == 0) {
            __syncthreads();
            if (t < E) baseS[t] = min(totS[t], CAP);   // mask_1_count
            __syncthreads();
        } else {
            if (t < E) g_used[t * 2 + b] = baseS[t] + min(totS[t], CAP - baseS[t]);
        }
    }
}

// ---------------- 3) gather tokens -> expert slot rows ----------------
__global__ void gather_kernel(const float4* __restrict__ x4)
{
    const int warp = threadIdx.x >> 5, lane = threadIdx.x & 31;
    const int a = blockIdx.x * 8 + warp;         // 0..16383 assignments
    const int tok = a >> 1, which = a & 1;
    const int slot = which ? g_s2[tok] : g_s1[tok];
    if (slot < 0) return;
    const int e = which ? g_i2[tok] : g_i1[tok];
    const int b = tok >> 12;
    const float4* src = x4 + (size_t)tok * (D / 4);
    float4* dst = g_ein4 + (((size_t)e * 2 + b) * CAP + slot) * (D / 4);
#pragma unroll
    for (int i = lane; i < D / 4; i += 32) dst[i] = src[i];
}

// ---------------- 4) tiled fp32 GEMM (shared by both FFN layers) ----------------
// WHICH==0: g_hid[e] = relu(g_ein[e] @ w1[e])   M=2048 K=512  N=2048
// WHICH==1: g_eout[e] = g_hid[e] @ w2[e]        M=2048 K=2048 N=512
template<int KDIM, int NDIM, bool RELU, int WHICH>
__global__ __launch_bounds__(256, 2) void gemm_kernel(const float4* __restrict__ Bw4)
{
    const int e  = blockIdx.z;
    const int m0 = blockIdx.y * 128;
    const int n0 = blockIdx.x * 128;
    const int batch = m0 >> 10;
    if ((m0 & 1023) >= g_used[e * 2 + batch]) return;   // skip unused slot rows

    const float4* __restrict__ A4 =
        (WHICH == 0 ? g_ein4 : g_hid4) + (size_t)e * ROWS_PER_E * (KDIM / 4);
    const float4* __restrict__ B4 = Bw4 + (size_t)e * KDIM * (NDIM / 4);
    float4* __restrict__       C4 =
        (WHICH == 0 ? g_hid4 : g_eout4) + (size_t)e * ROWS_PER_E * (NDIM / 4);

    __shared__ float As[16][132];   // transposed A tile, padded stride
    __shared__ float Bs[16][128];

    const int tid = threadIdx.x;
    const int tx = tid & 15, ty = tid >> 4;

    float acc[8][8];
#pragma unroll
    for (int i = 0; i < 8; i++)
#pragma unroll
        for (int j = 0; j < 8; j++) acc[i][j] = 0.f;

    for (int k0 = 0; k0 < KDIM; k0 += 16) {
#pragma unroll
        for (int r = 0; r < 2; r++) {
            const int idx = tid + r * 256;         // 0..511 float4 slots
            const int ar = idx >> 2;               // 0..127 rows
            const int ak4 = idx & 3;               // float4 index within 16 K
            const float4 v = A4[(size_t)(m0 + ar) * (KDIM / 4) + (k0 >> 2) + ak4];
            const int ak = ak4 << 2;
            As[ak + 0][ar] = v.x; As[ak + 1][ar] = v.y;
            As[ak + 2][ar] = v.z; As[ak + 3][ar] = v.w;
        }
#pragma unroll
        for (int r = 0; r < 2; r++) {
            const int idx = tid + r * 256;
            const int br = idx >> 5;               // 0..15
            const int bn4 = idx & 31;              // float4 index within 128 N
            *(float4*)&Bs[br][bn4 << 2] = B4[(size_t)(k0 + br) * (NDIM / 4) + (n0 >> 2) + bn4];
        }
        __syncthreads();
#pragma unroll
        for (int k = 0; k < 16; k++) {
            float a[8], bb[8];
            *(float4*)&a[0]  = *(const float4*)&As[k][ty * 8];
            *(float4*)&a[4]  = *(const float4*)&As[k][ty * 8 + 4];
            *(float4*)&bb[0] = *(const float4*)&Bs[k][tx * 8];
            *(float4*)&bb[4] = *(const float4*)&Bs[k][tx * 8 + 4];
#pragma unroll
            for (int i = 0; i < 8; i++)
#pragma unroll
                for (int j = 0; j < 8; j++) acc[i][j] = fmaf(a[i], bb[j], acc[i][j]);
        }
        __syncthreads();
    }
#pragma unroll
    for (int i = 0; i < 8; i++) {
        float4* cp = C4 + (size_t)(m0 + ty * 8 + i) * (NDIM / 4) + ((n0 + tx * 8) >> 2);
#pragma unroll
        for (int j = 0; j < 2; j++) {
            float4 v;
            v.x = acc[i][j * 4 + 0]; v.y = acc[i][j * 4 + 1];
            v.z = acc[i][j * 4 + 2]; v.w = acc[i][j * 4 + 3];
            if (RELU) {
                v.x = fmaxf(v.x, 0.f); v.y = fmaxf(v.y, 0.f);
                v.z = fmaxf(v.z, 0.f); v.w = fmaxf(v.w, 0.f);
            }
            cp[j] = v;
        }
    }
}

// ---------------- 5) combine: weighted sum back to token order ----------------
__global__ void combine_kernel(float4* __restrict__ out4)
{
    const int warp = threadIdx.x >> 5, lane = threadIdx.x & 31;
    const int tok = blockIdx.x * 8 + warp;
    const int b = tok >> 12;
    const int s1v = g_s1[tok], s2v = g_s2[tok];
    const float g1 = g_g1[tok], g2 = g_g2[tok];
    const bool h1 = s1v >= 0, h2 = s2v >= 0;
    const float4* p1 = g_eout4 + (((size_t)g_i1[tok] * 2 + b) * CAP + (h1 ? s1v : 0)) * (D / 4);
    const float4* p2 = g_eout4 + (((size_t)g_i2[tok] * 2 + b) * CAP + (h2 ? s2v : 0)) * (D / 4);
    float4* op = out4 + (size_t)tok * (D / 4);
#pragma unroll
    for (int i = lane; i < D / 4; i += 32) {
        float4 r = make_float4(0.f, 0.f, 0.f, 0.f);
        if (h1) { const float4 a = p1[i]; r.x = fmaf(g1, a.x, r.x); r.y = fmaf(g1, a.y, r.y);
                  r.z = fmaf(g1, a.z, r.z); r.w = fmaf(g1, a.w, r.w); }
        if (h2) { const float4 a = p2[i]; r.x = fmaf(g2, a.x, r.x); r.y = fmaf(g2, a.y, r.y);
                  r.z = fmaf(g2, a.z, r.z); r.w = fmaf(g2, a.w, r.w); }
        op[i] = r;
    }
}

// ---------------- launcher ----------------
extern "C" void kernel_launch(void* const* d_in, const int* in_sizes, int n_in,
                              void* d_out, int out_size)
{
    const float* x  = (const float*)d_in[0];   // [2,4096,512]
    const float* wg = (const float*)d_in[1];   // [512,16]
    const float4* w1 = (const float4*)d_in[2]; // [16,512,2048]
    const float4* w2 = (const float4*)d_in[3]; // [16,2048,512]
    float4* out = (float4*)d_out;              // [2,4096,512]

    gating_kernel<<<N_TOK / 8, 256>>>(x, wg);
    schedule_kernel<<<2, 512>>>();
    gather_kernel<<<16384 / 8, 256>>>((const float4*)x);

    dim3 grid1(H / 128, ROWS_PER_E / 128, E);   // (16,16,16)
    gemm_kernel<D, H, true, 0><<<grid1, 256>>>(w1);

    dim3 grid2(D / 128, ROWS_PER_E / 128, E);   // (4,16,16)
    gemm_kernel<H, D, false, 1><<<grid2, 256>>>(w2);

    combine_kernel<<<N_TOK / 8, 256>>>(out);
}

// round 13
// speedup vs baseline: 2.3759x; 2.3759x over previous
#include <cuda_runtime.h>
#include <cuda_bf16.h>
#include <cstdint>

#define N_TOK 8192
#define D     512
#define E     16
#define H     2048
#define CAP   1024
#define ROWS_PER_E 2048   // b * CAP

// ---------------- scratch (static device globals; proven R3 footprint) ----------------
__device__ float4 g_ein4 [(size_t)E * ROWS_PER_E * (D / 4)];   // expert inputs  f32
__device__ float4 g_hid4 [(size_t)E * ROWS_PER_E * (H / 4)];   // hidden         f32
__device__ float4 g_eout4[(size_t)E * ROWS_PER_E * (D / 4)];   // expert outputs f32
__device__ int   g_i1[N_TOK], g_i2[N_TOK];
__device__ int   g_s1[N_TOK], g_s2[N_TOK];
__device__ float g_g1[N_TOK], g_g2[N_TOK];
__device__ int   g_used[E * 2];

// ---------------- small helpers ----------------
__device__ __forceinline__ uint32_t smem_to_u32(const void* p) {
    uint32_t a;
    asm("{ .reg .u64 t; cvta.to.shared.u64 t, %1; cvt.u32.u64 %0, t; }" : "=r"(a) : "l"(p));
    return a;
}
__device__ __forceinline__ void ldmx4(uint32_t* r, uint32_t addr) {
    asm volatile("ldmatrix.sync.aligned.m8n8.x4.shared.b16 {%0,%1,%2,%3}, [%4];"
                 : "=r"(r[0]), "=r"(r[1]), "=r"(r[2]), "=r"(r[3]) : "r"(addr));
}
__device__ __forceinline__ void ldmx4t(uint32_t* r, uint32_t addr) {
    asm volatile("ldmatrix.sync.aligned.m8n8.x4.trans.shared.b16 {%0,%1,%2,%3}, [%4];"
                 : "=r"(r[0]), "=r"(r[1]), "=r"(r[2]), "=r"(r[3]) : "r"(addr));
}
__device__ __forceinline__ void mma16816(float* c, const uint32_t* a, const uint32_t* b) {
    asm volatile("mma.sync.aligned.m16n8k16.row.col.f32.bf16.bf16.f32 "
                 "{%0,%1,%2,%3}, {%4,%5,%6,%7}, {%8,%9}, {%0,%1,%2,%3};"
                 : "+f"(c[0]), "+f"(c[1]), "+f"(c[2]), "+f"(c[3])
                 : "r"(a[0]), "r"(a[1]), "r"(a[2]), "r"(a[3]), "r"(b[0]), "r"(b[1]));
}
// pack two floats into (hi bf16 x2) and (lo bf16 x2) words
__device__ __forceinline__ void split2(float a, float b, uint32_t& hi, uint32_t& lo) {
    __nv_bfloat16 h0 = __float2bfloat16(a);
    __nv_bfloat16 h1 = __float2bfloat16(b);
    __nv_bfloat16 l0 = __float2bfloat16(a - __bfloat162float(h0));
    __nv_bfloat16 l1 = __float2bfloat16(b - __bfloat162float(h1));
    __nv_bfloat162 hh = __halves2bfloat162(h0, h1);
    __nv_bfloat162 ll = __halves2bfloat162(l0, l1);
    hi = *(uint32_t*)&hh;
    lo = *(uint32_t*)&ll;
}

// ---------------- 1) gating (identical to R3 pass) ----------------
__global__ void gating_kernel(const float* __restrict__ x, const float* __restrict__ wg)
{
    __shared__ float wgs[E][D];
    const int tid = threadIdx.x;
    for (int i = tid; i < D * E; i += blockDim.x) wgs[i & (E - 1)][i >> 4] = wg[i];
    __syncthreads();

    const int lane = tid & 31, warp = tid >> 5;
    const int tok = blockIdx.x * (blockDim.x >> 5) + warp;
    const float* xp = x + (size_t)tok * D;

    float acc[E];
#pragma unroll
    for (int e = 0; e < E; e++) acc[e] = 0.f;
    for (int d = lane; d < D; d += 32) {
        const float xv = xp[d];
#pragma unroll
        for (int e = 0; e < E; e++) acc[e] = fmaf(xv, wgs[e][d], acc[e]);
    }
#pragma unroll
    for (int off = 16; off; off >>= 1)
#pragma unroll
        for (int e = 0; e < E; e++) acc[e] += __shfl_xor_sync(0xffffffffu, acc[e], off);

    if (lane == 0) {
        float m = acc[0];
#pragma unroll
        for (int e = 1; e < E; e++) m = fmaxf(m, acc[e]);
        float p[E]; float s = 0.f;
#pragma unroll
        for (int e = 0; e < E; e++) { p[e] = expf(acc[e] - m); s += p[e]; }
        int i1 = 0; float v1 = p[0];
#pragma unroll
        for (int e = 1; e < E; e++) if (p[e] > v1) { v1 = p[e]; i1 = e; }
        int i2 = -1; float v2 = -1.f;
#pragma unroll
        for (int e = 0; e < E; e++) if (e != i1 && p[e] > v2) { v2 = p[e]; i2 = e; }
        const float inv = 1.f / s;
        const float gate1 = v1 * inv, gate2 = v2 * inv;
        const float denom = gate1 + gate2 + 1e-9f;
        g_i1[tok] = i1;            g_i2[tok] = i2;
        g_g1[tok] = gate1 / denom; g_g2[tok] = gate2 / denom;
    }
}

// ---------------- 2) scheduler (identical to R3 pass) ----------------
__global__ void schedule_kernel()
{
    const int b    = blockIdx.x;
    const int t    = threadIdx.x;
    const int lane = t & 31, warp = t >> 5;
    __shared__ int warpTot[16][E];
    __shared__ int warpPre[16][E];
    __shared__ int totS[E];
    __shared__ int baseS[E];
    const int tokBase = b * 4096 + t * 8;

    for (int phase = 0; phase < 2; phase++) {
        const int* gidx = phase ? g_i2 : g_i1;
        int eidx[8];
#pragma unroll
        for (int k = 0; k < 8; k++) eidx[k] = gidx[tokBase + k];

        int inc[E], myc[E];
#pragma unroll
        for (int e = 0; e < E; e++) inc[e] = 0;
#pragma unroll
        for (int k = 0; k < 8; k++)
#pragma unroll
            for (int e = 0; e < E; e++) inc[e] += (eidx[k] == e);
#pragma unroll
        for (int e = 0; e < E; e++) myc[e] = inc[e];

        for (int off = 1; off < 32; off <<= 1) {
#pragma unroll
            for (int e = 0; e < E; e++) {
                const int v = __shfl_up_sync(0xffffffffu, inc[e], off);
                if (lane >= off) inc[e] += v;
            }
        }
        if (lane == 31) {
#pragma unroll
            for (int e = 0; e < E; e++) warpTot[warp][e] = inc[e];
        }
        __syncthreads();
        {
            const int v = (lane < 16) ? warpTot[lane][warp] : 0;
            int iv = v;
            for (int off = 1; off < 16; off <<= 1) {
                const int u = __shfl_up_sync(0xffffffffu, iv, off);
                if (lane >= off) iv += u;
            }
            if (lane < 16)  warpPre[lane][warp] = iv - v;
            if (lane == 15) totS[warp] = iv;
        }
        __syncthreads();

        int prefix[E];
#pragma unroll
        for (int e = 0; e < E; e++)
            prefix[e] = (phase ? baseS[e] : 0) + warpPre[warp][e] + (inc[e] - myc[e]);

#pragma unroll
        for (int k = 0; k < 8; k++) {
            int pos = 0;
#pragma unroll
            for (int j = 0; j < k; j++) pos += (eidx[j] == eidx[k]);
#pragma unroll
            for (int e = 0; e < E; e++) pos += (eidx[k] == e) ? prefix[e] : 0;
            const bool kept = pos < CAP;
            if (phase == 0) {
                g_s1[tokBase + k] = kept ? pos : -1;
                if (!kept) g_g1[tokBase + k] = 0.f;
            } else {
                g_s2[tokBase + k] = kept ? pos : -1;
                if (!kept) g_g2[tokBase + k] = 0.f;
            }
        }

        if (phase == 0) {
            __syncthreads();
            if (t < E) baseS[t] = min(totS[t], CAP);
            __syncthreads();
        } else {
            if (t < E) g_used[t * 2 + b] = baseS[t] + min(totS[t], CAP - baseS[t]);
        }
    }
}

// ---------------- 3) gather (identical to R3 pass, fp32) ----------------
__global__ void gather_kernel(const float4* __restrict__ x4)
{
    const int warp = threadIdx.x >> 5, lane = threadIdx.x & 31;
    const int a = blockIdx.x * 8 + warp;
    const int tok = a >> 1, which = a & 1;
    const int slot = which ? g_s2[tok] : g_s1[tok];
    if (slot < 0) return;
    const int e = which ? g_i2[tok] : g_i1[tok];
    const int b = tok >> 12;
    const float4* src = x4 + (size_t)tok * (D / 4);
    float4* dst = g_ein4 + (((size_t)e * 2 + b) * CAP + slot) * (D / 4);
#pragma unroll
    for (int i = lane; i < D / 4; i += 32) dst[i] = src[i];
}

// ---------------- 4) HMMA bf16x3 GEMM, fp32 in/out, on-the-fly split ----------------
// WHICH==0: g_hid = relu(g_ein @ w1)   KDIM=512   NDIM=2048   (w1: [e][K][N] f32)
// WHICH==1: g_eout = g_hid @ w2        KDIM=2048  NDIM=512    (w2: [e][K][N] f32)
// CTA tile 128x128, K-chunk 32, 8 warps (4m x 2n), warp tile 32x64.
// smem: Ah/Al 128 rows x 32 bf16 (stride 80B), Bh/Bl 32 k-rows x 128 bf16 (stride 272B).
// B fragments come from row-major [K][N] via ldmatrix.x4.trans. Total static smem 37888B.
#define A_ST   80
#define ATILE  (128 * A_ST)     // 10240
#define B_ST   272
#define BTILE  (32 * B_ST)      // 8704
#define B_OFF  (2 * ATILE)      // 20480
#define SM_TOT (2 * ATILE + 2 * BTILE)  // 37888

template<int KDIM, int NDIM, int WHICH>
__global__ void __launch_bounds__(256) hmma_ffn_kernel(const float* __restrict__ Bw)
{
    const int e  = blockIdx.z;
    const int m0 = blockIdx.y * 128;
    const int n0 = blockIdx.x * 128;
    if ((m0 & 1023) >= g_used[e * 2 + (m0 >> 10)]) return;

    __shared__ alignas(16) char sbuf[SM_TOT];
    const uint32_t sb = smem_to_u32(sbuf);
    const int tid = threadIdx.x, wid = tid >> 5, lane = tid & 31;
    const int warp_m = wid >> 1, warp_n = wid & 1;

    const float4* __restrict__ A4 =
        (const float4*)(WHICH ? (const void*)g_hid4 : (const void*)g_ein4) + (size_t)e * ROWS_PER_E * (KDIM / 4);
    const float4* __restrict__ B4 = (const float4*)Bw + (size_t)e * KDIM * (NDIM / 4);

    float acc[2][8][4];
#pragma unroll
    for (int i = 0; i < 2; i++)
#pragma unroll
        for (int j = 0; j < 8; j++)
#pragma unroll
            for (int k = 0; k < 4; k++) acc[i][j][k] = 0.f;

    const int NC = KDIM / 32;

#pragma unroll 1
    for (int c = 0; c < NC; c++) {
        const int k0 = c * 32;
        // ---- A tile: 128 rows x 32 k f32 -> bf16 hi/lo (1024 float4 slots) ----
#pragma unroll
        for (int i = 0; i < 4; i++) {
            const int idx = tid + i * 256;
            const int row = idx >> 3, seg = idx & 7;        // seg: float4 within 32 k
            const float4 v = A4[(size_t)(m0 + row) * (KDIM / 4) + (k0 >> 2) + seg];
            uint32_t h0, l0, h1, l1;
            split2(v.x, v.y, h0, l0);
            split2(v.z, v.w, h1, l1);
            *(uint2*)(sbuf + row * A_ST + seg * 8)         = make_uint2(h0, h1);
            *(uint2*)(sbuf + ATILE + row * A_ST + seg * 8) = make_uint2(l0, l1);
        }
        // ---- B tile: 32 k-rows x 128 n f32 -> bf16 hi/lo (1024 float4 slots) ----
#pragma unroll
        for (int i = 0; i < 4; i++) {
            const int idx = tid + i * 256;
            const int krow = idx >> 5, nseg = idx & 31;     // nseg: float4 within 128 n
            const float4 v = B4[(size_t)(k0 + krow) * (NDIM / 4) + (n0 >> 2) + nseg];
            uint32_t h0, l0, h1, l1;
            split2(v.x, v.y, h0, l0);
            split2(v.z, v.w, h1, l1);
            *(uint2*)(sbuf + B_OFF + krow * B_ST + nseg * 8)         = make_uint2(h0, h1);
            *(uint2*)(sbuf + B_OFF + BTILE + krow * B_ST + nseg * 8) = make_uint2(l0, l1);
        }
        __syncthreads();

#pragma unroll
        for (int ks = 0; ks < 2; ks++) {
            // A fragments (row-major, non-trans ldmatrix)
            uint32_t ah[2][4], al[2][4];
#pragma unroll
            for (int mf = 0; mf < 2; mf++) {
                const uint32_t ao = sb
                    + (uint32_t)(warp_m * 32 + mf * 16 + (lane & 15)) * A_ST
                    + (uint32_t)(ks * 2 + (lane >> 4)) * 16;
                ldmx4(ah[mf], ao);
                ldmx4(al[mf], ao + ATILE);
            }
            // B fragments from [k][n] rows via trans ldmatrix:
            // q = lane>>3: q0={k+0..7,nblk0} q1={k+8..15,nblk0} q2={k+0..7,nblk1} q3={k+8..15,nblk1}
            uint32_t bh[8][2], bl[8][2];
            const int q = lane >> 3;
#pragma unroll
            for (int np = 0; np < 4; np++) {
                const uint32_t bo = sb + B_OFF
                    + (uint32_t)(ks * 16 + (q & 1) * 8 + (lane & 7)) * B_ST
                    + (uint32_t)(warp_n * 64 + np * 16 + (q >> 1) * 8) * 2;
                uint32_t t[4];
                ldmx4t(t, bo);
                bh[2 * np][0] = t[0]; bh[2 * np][1] = t[1];
                bh[2 * np + 1][0] = t[2]; bh[2 * np + 1][1] = t[3];
                ldmx4t(t, bo + BTILE);
                bl[2 * np][0] = t[0]; bl[2 * np][1] = t[1];
                bl[2 * np + 1][0] = t[2]; bl[2 * np + 1][1] = t[3];
            }
#pragma unroll
            for (int nf = 0; nf < 8; nf++)
#pragma unroll
                for (int mf = 0; mf < 2; mf++) {
                    mma16816(acc[mf][nf], ah[mf], bh[nf]);
                    mma16816(acc[mf][nf], ah[mf], bl[nf]);
                    mma16816(acc[mf][nf], al[mf], bh[nf]);
                }
        }
        __syncthreads();
    }

    // ---- epilogue (fp32 out; relu for layer 1) ----
    float* __restrict__ C =
        (float*)(WHICH ? (void*)g_eout4 : (void*)g_hid4) + (size_t)e * ROWS_PER_E * NDIM;
    const int er0 = m0 + warp_m * 32 + (lane >> 2);
    const int ec0 = n0 + warp_n * 64 + 2 * (lane & 3);
#pragma unroll
    for (int mf = 0; mf < 2; mf++) {
#pragma unroll
        for (int nf = 0; nf < 8; nf++) {
#pragma unroll
            for (int half = 0; half < 2; half++) {
                const int rr = er0 + mf * 16 + half * 8;
                const int cc = ec0 + nf * 8;
                float v0 = acc[mf][nf][2 * half];
                float v1 = acc[mf][nf][2 * half + 1];
                if (WHICH == 0) { v0 = fmaxf(v0, 0.f); v1 = fmaxf(v1, 0.f); }
                *(float2*)(C + (size_t)rr * NDIM + cc) = make_float2(v0, v1);
            }
        }
    }
}

// ---------------- 5) combine (identical to R3 pass) ----------------
__global__ void combine_kernel(float4* __restrict__ out4)
{
    const int warp = threadIdx.x >> 5, lane = threadIdx.x & 31;
    const int tok = blockIdx.x * 8 + warp;
    const int b = tok >> 12;
    const int s1v = g_s1[tok], s2v = g_s2[tok];
    const float g1 = g_g1[tok], g2 = g_g2[tok];
    const bool h1 = s1v >= 0, h2 = s2v >= 0;
    const float4* p1 = g_eout4 + (((size_t)g_i1[tok] * 2 + b) * CAP + (h1 ? s1v : 0)) * (D / 4);
    const float4* p2 = g_eout4 + (((size_t)g_i2[tok] * 2 + b) * CAP + (h2 ? s2v : 0)) * (D / 4);
    float4* op = out4 + (size_t)tok * (D / 4);
#pragma unroll
    for (int i = lane; i < D / 4; i += 32) {
        float4 r = make_float4(0.f, 0.f, 0.f, 0.f);
        if (h1) { const float4 a = p1[i]; r.x = fmaf(g1, a.x, r.x); r.y = fmaf(g1, a.y, r.y);
                  r.z = fmaf(g1, a.z, r.z); r.w = fmaf(g1, a.w, r.w); }
        if (h2) { const float4 a = p2[i]; r.x = fmaf(g2, a.x, r.x); r.y = fmaf(g2, a.y, r.y);
                  r.z = fmaf(g2, a.z, r.z); r.w = fmaf(g2, a.w, r.w); }
        op[i] = r;
    }
}

// ---------------- launcher ----------------
extern "C" void kernel_launch(void* const* d_in, const int* in_sizes, int n_in,
                              void* d_out, int out_size)
{
    const float* x  = (const float*)d_in[0];   // [2,4096,512]
    const float* wg = (const float*)d_in[1];   // [512,16]
    const float* w1 = (const float*)d_in[2];   // [16,512,2048]
    const float* w2 = (const float*)d_in[3];   // [16,2048,512]
    float4* out = (float4*)d_out;              // [2,4096,512]

    gating_kernel<<<N_TOK / 8, 256>>>(x, wg);
    schedule_kernel<<<2, 512>>>();
    gather_kernel<<<16384 / 8, 256>>>((const float4*)x);

    hmma_ffn_kernel<D, H, 0><<<dim3(H / 128, ROWS_PER_E / 128, E), 256>>>(w1);
    hmma_ffn_kernel<H, D, 1><<<dim3(D / 128, ROWS_PER_E / 128, E), 256>>>(w2);

    combine_kernel<<<N_TOK / 8, 256>>>(out);
}

// round 14
// speedup vs baseline: 2.5711x; 1.0822x over previous
#include <cuda_runtime.h>
#include <cuda_bf16.h>
#include <cstdint>

#define N_TOK 8192
#define D     512
#define E     16
#define H     2048
#define CAP   1024
#define ROWS_PER_E 2048   // b * CAP

// ---------------- scratch (static device globals; proven R13 footprint) ----------------
__device__ float4 g_ein4 [(size_t)E * ROWS_PER_E * (D / 4)];   // expert inputs  f32
__device__ float4 g_hid4 [(size_t)E * ROWS_PER_E * (H / 4)];   // hidden         f32
__device__ float4 g_eout4[(size_t)E * ROWS_PER_E * (D / 4)];   // expert outputs f32
__device__ int   g_i1[N_TOK], g_i2[N_TOK];
__device__ int   g_s1[N_TOK], g_s2[N_TOK];
__device__ float g_g1[N_TOK], g_g2[N_TOK];
__device__ int   g_used[E * 2];

// ---------------- small helpers ----------------
__device__ __forceinline__ uint32_t smem_to_u32(const void* p) {
    uint32_t a;
    asm("{ .reg .u64 t; cvta.to.shared.u64 t, %1; cvt.u32.u64 %0, t; }" : "=r"(a) : "l"(p));
    return a;
}
__device__ __forceinline__ void ldmx4(uint32_t* r, uint32_t addr) {
    asm volatile("ldmatrix.sync.aligned.m8n8.x4.shared.b16 {%0,%1,%2,%3}, [%4];"
                 : "=r"(r[0]), "=r"(r[1]), "=r"(r[2]), "=r"(r[3]) : "r"(addr));
}
__device__ __forceinline__ void ldmx4t(uint32_t* r, uint32_t addr) {
    asm volatile("ldmatrix.sync.aligned.m8n8.x4.trans.shared.b16 {%0,%1,%2,%3}, [%4];"
                 : "=r"(r[0]), "=r"(r[1]), "=r"(r[2]), "=r"(r[3]) : "r"(addr));
}
__device__ __forceinline__ void mma16816(float* c, const uint32_t* a, const uint32_t* b) {
    asm volatile("mma.sync.aligned.m16n8k16.row.col.f32.bf16.bf16.f32 "
                 "{%0,%1,%2,%3}, {%4,%5,%6,%7}, {%8,%9}, {%0,%1,%2,%3};"
                 : "+f"(c[0]), "+f"(c[1]), "+f"(c[2]), "+f"(c[3])
                 : "r"(a[0]), "r"(a[1]), "r"(a[2]), "r"(a[3]), "r"(b[0]), "r"(b[1]));
}
// pack two floats into (hi bf16 x2) and (lo bf16 x2) words
__device__ __forceinline__ void split2(float a, float b, uint32_t& hi, uint32_t& lo) {
    __nv_bfloat16 h0 = __float2bfloat16(a);
    __nv_bfloat16 h1 = __float2bfloat16(b);
    __nv_bfloat16 l0 = __float2bfloat16(a - __bfloat162float(h0));
    __nv_bfloat16 l1 = __float2bfloat16(b - __bfloat162float(h1));
    __nv_bfloat162 hh = __halves2bfloat162(h0, h1);
    __nv_bfloat162 ll = __halves2bfloat162(l0, l1);
    hi = *(uint32_t*)&hh;
    lo = *(uint32_t*)&ll;
}

// ---------------- 1) gating (identical to R13 pass) ----------------
__global__ void gating_kernel(const float* __restrict__ x, const float* __restrict__ wg)
{
    __shared__ float wgs[E][D];
    const int tid = threadIdx.x;
    for (int i = tid; i < D * E; i += blockDim.x) wgs[i & (E - 1)][i >> 4] = wg[i];
    __syncthreads();

    const int lane = tid & 31, warp = tid >> 5;
    const int tok = blockIdx.x * (blockDim.x >> 5) + warp;
    const float* xp = x + (size_t)tok * D;

    float acc[E];
#pragma unroll
    for (int e = 0; e < E; e++) acc[e] = 0.f;
    for (int d = lane; d < D; d += 32) {
        const float xv = xp[d];
#pragma unroll
        for (int e = 0; e < E; e++) acc[e] = fmaf(xv, wgs[e][d], acc[e]);
    }
#pragma unroll
    for (int off = 16; off; off >>= 1)
#pragma unroll
        for (int e = 0; e < E; e++) acc[e] += __shfl_xor_sync(0xffffffffu, acc[e], off);

    if (lane == 0) {
        float m = acc[0];
#pragma unroll
        for (int e = 1; e < E; e++) m = fmaxf(m, acc[e]);
        float p[E]; float s = 0.f;
#pragma unroll
        for (int e = 0; e < E; e++) { p[e] = expf(acc[e] - m); s += p[e]; }
        int i1 = 0; float v1 = p[0];
#pragma unroll
        for (int e = 1; e < E; e++) if (p[e] > v1) { v1 = p[e]; i1 = e; }
        int i2 = -1; float v2 = -1.f;
#pragma unroll
        for (int e = 0; e < E; e++) if (e != i1 && p[e] > v2) { v2 = p[e]; i2 = e; }
        const float inv = 1.f / s;
        const float gate1 = v1 * inv, gate2 = v2 * inv;
        const float denom = gate1 + gate2 + 1e-9f;
        g_i1[tok] = i1;            g_i2[tok] = i2;
        g_g1[tok] = gate1 / denom; g_g2[tok] = gate2 / denom;
    }
}

// ---------------- 2) scheduler (identical to R13 pass) ----------------
__global__ void schedule_kernel()
{
    const int b    = blockIdx.x;
    const int t    = threadIdx.x;
    const int lane = t & 31, warp = t >> 5;
    __shared__ int warpTot[16][E];
    __shared__ int warpPre[16][E];
    __shared__ int totS[E];
    __shared__ int baseS[E];
    const int tokBase = b * 4096 + t * 8;

    for (int phase = 0; phase < 2; phase++) {
        const int* gidx = phase ? g_i2 : g_i1;
        int eidx[8];
#pragma unroll
        for (int k = 0; k < 8; k++) eidx[k] = gidx[tokBase + k];

        int inc[E], myc[E];
#pragma unroll
        for (int e = 0; e < E; e++) inc[e] = 0;
#pragma unroll
        for (int k = 0; k < 8; k++)
#pragma unroll
            for (int e = 0; e < E; e++) inc[e] += (eidx[k] == e);
#pragma unroll
        for (int e = 0; e < E; e++) myc[e] = inc[e];

        for (int off = 1; off < 32; off <<= 1) {
#pragma unroll
            for (int e = 0; e < E; e++) {
                const int v = __shfl_up_sync(0xffffffffu, inc[e], off);
                if (lane >= off) inc[e] += v;
            }
        }
        if (lane == 31) {
#pragma unroll
            for (int e = 0; e < E; e++) warpTot[warp][e] = inc[e];
        }
        __syncthreads();
        {
            const int v = (lane < 16) ? warpTot[lane][warp] : 0;
            int iv = v;
            for (int off = 1; off < 16; off <<= 1) {
                const int u = __shfl_up_sync(0xffffffffu, iv, off);
                if (lane >= off) iv += u;
            }
            if (lane < 16)  warpPre[lane][warp] = iv - v;
            if (lane == 15) totS[warp] = iv;
        }
        __syncthreads();

        int prefix[E];
#pragma unroll
        for (int e = 0; e < E; e++)
            prefix[e] = (phase ? baseS[e] : 0) + warpPre[warp][e] + (inc[e] - myc[e]);

#pragma unroll
        for (int k = 0; k < 8; k++) {
            int pos = 0;
#pragma unroll
            for (int j = 0; j < k; j++) pos += (eidx[j] == eidx[k]);
#pragma unroll
            for (int e = 0; e < E; e++) pos += (eidx[k] == e) ? prefix[e] : 0;
            const bool kept = pos < CAP;
            if (phase == 0) {
                g_s1[tokBase + k] = kept ? pos : -1;
                if (!kept) g_g1[tokBase + k] = 0.f;
            } else {
                g_s2[tokBase + k] = kept ? pos : -1;
                if (!kept) g_g2[tokBase + k] = 0.f;
            }
        }

        if (phase == 0) {
            __syncthreads();
            if (t < E) baseS[t] = min(totS[t], CAP);
            __syncthreads();
        } else {
            if (t < E) g_used[t * 2 + b] = baseS[t] + min(totS[t], CAP - baseS[t]);
        }
    }
}

// ---------------- 3) gather (identical to R13 pass, fp32) ----------------
__global__ void gather_kernel(const float4* __restrict__ x4)
{
    const int warp = threadIdx.x >> 5, lane = threadIdx.x & 31;
    const int a = blockIdx.x * 8 + warp;
    const int tok = a >> 1, which = a & 1;
    const int slot = which ? g_s2[tok] : g_s1[tok];
    if (slot < 0) return;
    const int e = which ? g_i2[tok] : g_i1[tok];
    const int b = tok >> 12;
    const float4* src = x4 + (size_t)tok * (D / 4);
    float4* dst = g_ein4 + (((size_t)e * 2 + b) * CAP + slot) * (D / 4);
#pragma unroll
    for (int i = lane; i < D / 4; i += 32) dst[i] = src[i];
}

// ---------------- 4) HMMA bf16x3 GEMM, double-buffered with register prefetch ----------------
// WHICH==0: g_hid = relu(g_ein @ w1)   KDIM=512   NDIM=2048   (w1: [e][K][N] f32)
// WHICH==1: g_eout = g_hid @ w2        KDIM=2048  NDIM=512    (w2: [e][K][N] f32)
// CTA tile 128x128, K-chunk 16, 8 warps (4m x 2n), warp tile 32x64.
// Per buffer: Ah/Al 128 rows x 16 bf16 (stride 48B), Bh/Bl 16 k-rows x 128 bf16 (stride 272B)
//   = 20992 B; two buffers = 41984 B static smem. One __syncthreads per K-chunk.
#define A_ST   48
#define ATILE  (128 * A_ST)              // 6144
#define B_ST   272
#define BTILE  (16 * B_ST)               // 4352
#define B_OFF  (2 * ATILE)               // 12288
#define BUFSZ  (B_OFF + 2 * BTILE)       // 20992

template<int KDIM, int NDIM, int WHICH>
__global__ void __launch_bounds__(256, 2) hmma_ffn_kernel(const float* __restrict__ Bw)
{
    const int e  = blockIdx.z;
    const int m0 = blockIdx.y * 128;
    const int n0 = blockIdx.x * 128;
    if ((m0 & 1023) >= g_used[e * 2 + (m0 >> 10)]) return;

    __shared__ alignas(16) char sbuf[2 * BUFSZ];
    const uint32_t sb = smem_to_u32(sbuf);
    const int tid = threadIdx.x, wid = tid >> 5, lane = tid & 31;
    const int warp_m = wid >> 1, warp_n = wid & 1;

    const float4* __restrict__ A4 =
        (const float4*)(WHICH ? (const void*)g_hid4 : (const void*)g_ein4) + (size_t)e * ROWS_PER_E * (KDIM / 4);
    const float4* __restrict__ B4 = (const float4*)Bw + (size_t)e * KDIM * (NDIM / 4);

    float acc[2][8][4];
#pragma unroll
    for (int i = 0; i < 2; i++)
#pragma unroll
        for (int j = 0; j < 8; j++)
#pragma unroll
            for (int k = 0; k < 4; k++) acc[i][j][k] = 0.f;

    const int NC = KDIM / 16;
    // loader geometry: A chunk = 128 rows x 4 float4; B chunk = 16 k-rows x 32 float4
    const int aRow = tid >> 2, aSeg = tid & 3;   // +64 rows for second element
    const int bKr  = tid >> 5, bNs = tid & 31;   // +8 k-rows for second element

    float4 pa[2], pb[2];
    auto gload = [&](int c) {
        pa[0] = A4[(size_t)(m0 + aRow)      * (KDIM / 4) + c * 4 + aSeg];
        pa[1] = A4[(size_t)(m0 + aRow + 64) * (KDIM / 4) + c * 4 + aSeg];
        pb[0] = B4[(size_t)(c * 16 + bKr)     * (NDIM / 4) + (n0 >> 2) + bNs];
        pb[1] = B4[(size_t)(c * 16 + bKr + 8) * (NDIM / 4) + (n0 >> 2) + bNs];
    };
    auto sstore = [&](int c) {
        char* bp = sbuf + (c & 1) * BUFSZ;
#pragma unroll
        for (int i = 0; i < 2; i++) {
            uint32_t h0, l0, h1, l1;
            const int row = aRow + i * 64;
            split2(pa[i].x, pa[i].y, h0, l0);
            split2(pa[i].z, pa[i].w, h1, l1);
            *(uint2*)(bp + row * A_ST + aSeg * 8)         = make_uint2(h0, h1);
            *(uint2*)(bp + ATILE + row * A_ST + aSeg * 8) = make_uint2(l0, l1);
            const int kr = bKr + i * 8;
            split2(pb[i].x, pb[i].y, h0, l0);
            split2(pb[i].z, pb[i].w, h1, l1);
            *(uint2*)(bp + B_OFF + kr * B_ST + bNs * 8)         = make_uint2(h0, h1);
            *(uint2*)(bp + B_OFF + BTILE + kr * B_ST + bNs * 8) = make_uint2(l0, l1);
        }
    };

    gload(0);
#pragma unroll 1
    for (int c = 0; c < NC; c++) {
        sstore(c);
        if (c + 1 < NC) gload(c + 1);     // latency overlaps with compute below
        __syncthreads();

        const uint32_t bb = sb + (c & 1) * BUFSZ;
        // A fragments (row-major, non-trans ldmatrix), mapping verified in R13
        uint32_t ah[2][4], al[2][4];
#pragma unroll
        for (int mf = 0; mf < 2; mf++) {
            const uint32_t ao = bb
                + (uint32_t)(warp_m * 32 + mf * 16 + (lane & 15)) * A_ST
                + (uint32_t)(lane >> 4) * 16;
            ldmx4(ah[mf], ao);
            ldmx4(al[mf], ao + ATILE);
        }
        // B fragments from [k][n] via trans ldmatrix (R13-verified mapping, ks=0),
        // interleaved with MMAs to keep only 8 live B registers.
        const int q = lane >> 3;
#pragma unroll
        for (int np = 0; np < 4; np++) {
            const uint32_t bo = bb + B_OFF
                + (uint32_t)((q & 1) * 8 + (lane & 7)) * B_ST
                + (uint32_t)(warp_n * 64 + np * 16 + (q >> 1) * 8) * 2;
            uint32_t t[4], u[4];
            ldmx4t(t, bo);           // bh pair for nf = 2np, 2np+1
            ldmx4t(u, bo + BTILE);   // bl pair
#pragma unroll
            for (int mf = 0; mf < 2; mf++) {
                mma16816(acc[mf][2 * np],     ah[mf], &t[0]);
                mma16816(acc[mf][2 * np + 1], ah[mf], &t[2]);
                mma16816(acc[mf][2 * np],     al[mf], &t[0]);
                mma16816(acc[mf][2 * np + 1], al[mf], &t[2]);
                mma16816(acc[mf][2 * np],     ah[mf], &u[0]);
                mma16816(acc[mf][2 * np + 1], ah[mf], &u[2]);
            }
        }
        // no trailing sync: next iteration stores to the OTHER buffer; reuse of this
        // buffer happens after the next iteration's __syncthreads.
    }

    // ---- epilogue (fp32 out; relu for layer 1) ----
    float* __restrict__ C =
        (float*)(WHICH ? (void*)g_eout4 : (void*)g_hid4) + (size_t)e * ROWS_PER_E * NDIM;
    const int er0 = m0 + warp_m * 32 + (lane >> 2);
    const int ec0 = n0 + warp_n * 64 + 2 * (lane & 3);
#pragma unroll
    for (int mf = 0; mf < 2; mf++) {
#pragma unroll
        for (int nf = 0; nf < 8; nf++) {
#pragma unroll
            for (int half = 0; half < 2; half++) {
                const int rr = er0 + mf * 16 + half * 8;
                const int cc = ec0 + nf * 8;
                float v0 = acc[mf][nf][2 * half];
                float v1 = acc[mf][nf][2 * half + 1];
                if (WHICH == 0) { v0 = fmaxf(v0, 0.f); v1 = fmaxf(v1, 0.f); }
                *(float2*)(C + (size_t)rr * NDIM + cc) = make_float2(v0, v1);
            }
        }
    }
}

// ---------------- 5) combine (identical to R13 pass) ----------------
__global__ void combine_kernel(float4* __restrict__ out4)
{
    const int warp = threadIdx.x >> 5, lane = threadIdx.x & 31;
    const int tok = blockIdx.x * 8 + warp;
    const int b = tok >> 12;
    const int s1v = g_s1[tok], s2v = g_s2[tok];
    const float g1 = g_g1[tok], g2 = g_g2[tok];
    const bool h1 = s1v >= 0, h2 = s2v >= 0;
    const float4* p1 = g_eout4 + (((size_t)g_i1[tok] * 2 + b) * CAP + (h1 ? s1v : 0)) * (D / 4);
    const float4* p2 = g_eout4 + (((size_t)g_i2[tok] * 2 + b) * CAP + (h2 ? s2v : 0)) * (D / 4);
    float4* op = out4 + (size_t)tok * (D / 4);
#pragma unroll
    for (int i = lane; i < D / 4; i += 32) {
        float4 r = make_float4(0.f, 0.f, 0.f, 0.f);
        if (h1) { const float4 a = p1[i]; r.x = fmaf(g1, a.x, r.x); r.y = fmaf(g1, a.y, r.y);
                  r.z = fmaf(g1, a.z, r.z); r.w = fmaf(g1, a.w, r.w); }
        if (h2) { const float4 a = p2[i]; r.x = fmaf(g2, a.x, r.x); r.y = fmaf(g2, a.y, r.y);
                  r.z = fmaf(g2, a.z, r.z); r.w = fmaf(g2, a.w, r.w); }
        op[i] = r;
    }
}

// ---------------- launcher ----------------
extern "C" void kernel_launch(void* const* d_in, const int* in_sizes, int n_in,
                              void* d_out, int out_size)
{
    const float* x  = (const float*)d_in[0];   // [2,4096,512]
    const float* wg = (const float*)d_in[1];   // [512,16]
    const float* w1 = (const float*)d_in[2];   // [16,512,2048]
    const float* w2 = (const float*)d_in[3];   // [16,2048,512]
    float4* out = (float4*)d_out;              // [2,4096,512]

    gating_kernel<<<N_TOK / 8, 256>>>(x, wg);
    schedule_kernel<<<2, 512>>>();
    gather_kernel<<<16384 / 8, 256>>>((const float4*)x);

    hmma_ffn_kernel<D, H, 0><<<dim3(H / 128, ROWS_PER_E / 128, E), 256>>>(w1);
    hmma_ffn_kernel<H, D, 1><<<dim3(D / 128, ROWS_PER_E / 128, E), 256>>>(w2);

    combine_kernel<<<N_TOK / 8, 256>>>(out);
}

// round 15
// speedup vs baseline: 2.6448x; 1.0286x over previous
#include <cuda_runtime.h>
#include <cuda_bf16.h>
#include <cstdint>

#define N_TOK 8192
#define D     512
#define E     16
#define H     2048
#define CAP   1024
#define ROWS_PER_E 2048   // b * CAP

// ---------------- scratch (static device globals; proven R13 footprint) ----------------
__device__ float4 g_ein4 [(size_t)E * ROWS_PER_E * (D / 4)];   // expert inputs  f32
__device__ float4 g_hid4 [(size_t)E * ROWS_PER_E * (H / 4)];   // hidden         f32
__device__ float4 g_eout4[(size_t)E * ROWS_PER_E * (D / 4)];   // expert outputs f32
__device__ int   g_i1[N_TOK], g_i2[N_TOK];
__device__ int   g_s1[N_TOK], g_s2[N_TOK];
__device__ float g_g1[N_TOK], g_g2[N_TOK];
__device__ int   g_used[E * 2];

// ---------------- small helpers ----------------
__device__ __forceinline__ uint32_t smem_to_u32(const void* p) {
    uint32_t a;
    asm("{ .reg .u64 t; cvta.to.shared.u64 t, %1; cvt.u32.u64 %0, t; }" : "=r"(a) : "l"(p));
    return a;
}
__device__ __forceinline__ void ldmx4(uint32_t* r, uint32_t addr) {
    asm volatile("ldmatrix.sync.aligned.m8n8.x4.shared.b16 {%0,%1,%2,%3}, [%4];"
                 : "=r"(r[0]), "=r"(r[1]), "=r"(r[2]), "=r"(r[3]) : "r"(addr));
}
__device__ __forceinline__ void ldmx4t(uint32_t* r, uint32_t addr) {
    asm volatile("ldmatrix.sync.aligned.m8n8.x4.trans.shared.b16 {%0,%1,%2,%3}, [%4];"
                 : "=r"(r[0]), "=r"(r[1]), "=r"(r[2]), "=r"(r[3]) : "r"(addr));
}
__device__ __forceinline__ void mma16816(float* c, const uint32_t* a, const uint32_t* b) {
    asm volatile("mma.sync.aligned.m16n8k16.row.col.f32.bf16.bf16.f32 "
                 "{%0,%1,%2,%3}, {%4,%5,%6,%7}, {%8,%9}, {%0,%1,%2,%3};"
                 : "+f"(c[0]), "+f"(c[1]), "+f"(c[2]), "+f"(c[3])
                 : "r"(a[0]), "r"(a[1]), "r"(a[2]), "r"(a[3]), "r"(b[0]), "r"(b[1]));
}
// pack two floats into (hi bf16 x2) and (lo bf16 x2) words
__device__ __forceinline__ void split2(float a, float b, uint32_t& hi, uint32_t& lo) {
    __nv_bfloat16 h0 = __float2bfloat16(a);
    __nv_bfloat16 h1 = __float2bfloat16(b);
    __nv_bfloat16 l0 = __float2bfloat16(a - __bfloat162float(h0));
    __nv_bfloat16 l1 = __float2bfloat16(b - __bfloat162float(h1));
    __nv_bfloat162 hh = __halves2bfloat162(h0, h1);
    __nv_bfloat162 ll = __halves2bfloat162(l0, l1);
    hi = *(uint32_t*)&hh;
    lo = *(uint32_t*)&ll;
}

// ---------------- 1) gating (identical to R13 pass) ----------------
__global__ void gating_kernel(const float* __restrict__ x, const float* __restrict__ wg)
{
    __shared__ float wgs[E][D];
    const int tid = threadIdx.x;
    for (int i = tid; i < D * E; i += blockDim.x) wgs[i & (E - 1)][i >> 4] = wg[i];
    __syncthreads();

    const int lane = tid & 31, warp = tid >> 5;
    const int tok = blockIdx.x * (blockDim.x >> 5) + warp;
    const float* xp = x + (size_t)tok * D;

    float acc[E];
#pragma unroll
    for (int e = 0; e < E; e++) acc[e] = 0.f;
    for (int d = lane; d < D; d += 32) {
        const float xv = xp[d];
#pragma unroll
        for (int e = 0; e < E; e++) acc[e] = fmaf(xv, wgs[e][d], acc[e]);
    }
#pragma unroll
    for (int off = 16; off; off >>= 1)
#pragma unroll
        for (int e = 0; e < E; e++) acc[e] += __shfl_xor_sync(0xffffffffu, acc[e], off);

    if (lane == 0) {
        float m = acc[0];
#pragma unroll
        for (int e = 1; e < E; e++) m = fmaxf(m, acc[e]);
        float p[E]; float s = 0.f;
#pragma unroll
        for (int e = 0; e < E; e++) { p[e] = expf(acc[e] - m); s += p[e]; }
        int i1 = 0; float v1 = p[0];
#pragma unroll
        for (int e = 1; e < E; e++) if (p[e] > v1) { v1 = p[e]; i1 = e; }
        int i2 = -1; float v2 = -1.f;
#pragma unroll
        for (int e = 0; e < E; e++) if (e != i1 && p[e] > v2) { v2 = p[e]; i2 = e; }
        const float inv = 1.f / s;
        const float gate1 = v1 * inv, gate2 = v2 * inv;
        const float denom = gate1 + gate2 + 1e-9f;
        g_i1[tok] = i1;            g_i2[tok] = i2;
        g_g1[tok] = gate1 / denom; g_g2[tok] = gate2 / denom;
    }
}

// ---------------- 2) scheduler (identical to R13 pass) ----------------
__global__ void schedule_kernel()
{
    const int b    = blockIdx.x;
    const int t    = threadIdx.x;
    const int lane = t & 31, warp = t >> 5;
    __shared__ int warpTot[16][E];
    __shared__ int warpPre[16][E];
    __shared__ int totS[E];
    __shared__ int baseS[E];
    const int tokBase = b * 4096 + t * 8;

    for (int phase = 0; phase < 2; phase++) {
        const int* gidx = phase ? g_i2 : g_i1;
        int eidx[8];
#pragma unroll
        for (int k = 0; k < 8; k++) eidx[k] = gidx[tokBase + k];

        int inc[E], myc[E];
#pragma unroll
        for (int e = 0; e < E; e++) inc[e] = 0;
#pragma unroll
        for (int k = 0; k < 8; k++)
#pragma unroll
            for (int e = 0; e < E; e++) inc[e] += (eidx[k] == e);
#pragma unroll
        for (int e = 0; e < E; e++) myc[e] = inc[e];

        for (int off = 1; off < 32; off <<= 1) {
#pragma unroll
            for (int e = 0; e < E; e++) {
                const int v = __shfl_up_sync(0xffffffffu, inc[e], off);
                if (lane >= off) inc[e] += v;
            }
        }
        if (lane == 31) {
#pragma unroll
            for (int e = 0; e < E; e++) warpTot[warp][e] = inc[e];
        }
        __syncthreads();
        {
            const int v = (lane < 16) ? warpTot[lane][warp] : 0;
            int iv = v;
            for (int off = 1; off < 16; off <<= 1) {
                const int u = __shfl_up_sync(0xffffffffu, iv, off);
                if (lane >= off) iv += u;
            }
            if (lane < 16)  warpPre[lane][warp] = iv - v;
            if (lane == 15) totS[warp] = iv;
        }
        __syncthreads();

        int prefix[E];
#pragma unroll
        for (int e = 0; e < E; e++)
            prefix[e] = (phase ? baseS[e] : 0) + warpPre[warp][e] + (inc[e] - myc[e]);

#pragma unroll
        for (int k = 0; k < 8; k++) {
            int pos = 0;
#pragma unroll
            for (int j = 0; j < k; j++) pos += (eidx[j] == eidx[k]);
#pragma unroll
            for (int e = 0; e < E; e++) pos += (eidx[k] == e) ? prefix[e] : 0;
            const bool kept = pos < CAP;
            if (phase == 0) {
                g_s1[tokBase + k] = kept ? pos : -1;
                if (!kept) g_g1[tokBase + k] = 0.f;
            } else {
                g_s2[tokBase + k] = kept ? pos : -1;
                if (!kept) g_g2[tokBase + k] = 0.f;
            }
        }

        if (phase == 0) {
            __syncthreads();
            if (t < E) baseS[t] = min(totS[t], CAP);
            __syncthreads();
        } else {
            if (t < E) g_used[t * 2 + b] = baseS[t] + min(totS[t], CAP - baseS[t]);
        }
    }
}

// ---------------- 3) gather (identical to R13 pass, fp32) ----------------
__global__ void gather_kernel(const float4* __restrict__ x4)
{
    const int warp = threadIdx.x >> 5, lane = threadIdx.x & 31;
    const int a = blockIdx.x * 8 + warp;
    const int tok = a >> 1, which = a & 1;
    const int slot = which ? g_s2[tok] : g_s1[tok];
    if (slot < 0) return;
    const int e = which ? g_i2[tok] : g_i1[tok];
    const int b = tok >> 12;
    const float4* src = x4 + (size_t)tok * (D / 4);
    float4* dst = g_ein4 + (((size_t)e * 2 + b) * CAP + slot) * (D / 4);
#pragma unroll
    for (int i = lane; i < D / 4; i += 32) dst[i] = src[i];
}

// ---------------- 4) HMMA bf16x3 GEMM, store-overlapped double buffer ----------------
// WHICH==0: g_hid = relu(g_ein @ w1)   KDIM=512   NDIM=2048   (w1: [e][K][N] f32)
// WHICH==1: g_eout = g_hid @ w2        KDIM=2048  NDIM=512    (w2: [e][K][N] f32)
// CTA tile 128x128, K-chunk 16, 8 warps (4m x 2n), warp tile 32x64.
// Pipeline: regs hold chunk c+1 while computing c; sstore(c+1)+gload(c+2) are issued
// INSIDE the compute region (they target the other buffer) with one barrier per chunk.
// MMA order round-robins 4 accumulators per np-group -> RAW distance 4.
#define A_ST   48
#define ATILE  (128 * A_ST)              // 6144
#define B_ST   272
#define BTILE  (16 * B_ST)               // 4352
#define B_OFF  (2 * ATILE)               // 12288
#define BUFSZ  (B_OFF + 2 * BTILE)       // 20992

template<int KDIM, int NDIM, int WHICH>
__global__ void __launch_bounds__(256, 2) hmma_ffn_kernel(const float* __restrict__ Bw)
{
    const int e  = blockIdx.z;
    const int m0 = blockIdx.y * 128;
    const int n0 = blockIdx.x * 128;
    if ((m0 & 1023) >= g_used[e * 2 + (m0 >> 10)]) return;

    __shared__ alignas(16) char sbuf[2 * BUFSZ];
    const uint32_t sb = smem_to_u32(sbuf);
    const int tid = threadIdx.x, wid = tid >> 5, lane = tid & 31;
    const int warp_m = wid >> 1, warp_n = wid & 1;

    const float4* __restrict__ A4 =
        (const float4*)(WHICH ? (const void*)g_hid4 : (const void*)g_ein4) + (size_t)e * ROWS_PER_E * (KDIM / 4);
    const float4* __restrict__ B4 = (const float4*)Bw + (size_t)e * KDIM * (NDIM / 4);

    float acc[2][8][4];
#pragma unroll
    for (int i = 0; i < 2; i++)
#pragma unroll
        for (int j = 0; j < 8; j++)
#pragma unroll
            for (int k = 0; k < 4; k++) acc[i][j][k] = 0.f;

    const int NC = KDIM / 16;
    // loader geometry: A chunk = 128 rows x 4 float4; B chunk = 16 k-rows x 32 float4
    const int aRow = tid >> 2, aSeg = tid & 3;   // +64 rows for second element
    const int bKr  = tid >> 5, bNs = tid & 31;   // +8 k-rows for second element

    float4 pa[2], pb[2];
    auto gload = [&](int c) {
        pa[0] = A4[(size_t)(m0 + aRow)      * (KDIM / 4) + c * 4 + aSeg];
        pa[1] = A4[(size_t)(m0 + aRow + 64) * (KDIM / 4) + c * 4 + aSeg];
        pb[0] = B4[(size_t)(c * 16 + bKr)     * (NDIM / 4) + (n0 >> 2) + bNs];
        pb[1] = B4[(size_t)(c * 16 + bKr + 8) * (NDIM / 4) + (n0 >> 2) + bNs];
    };
    auto sstore = [&](int c) {
        char* bp = sbuf + (c & 1) * BUFSZ;
#pragma unroll
        for (int i = 0; i < 2; i++) {
            uint32_t h0, l0, h1, l1;
            const int row = aRow + i * 64;
            split2(pa[i].x, pa[i].y, h0, l0);
            split2(pa[i].z, pa[i].w, h1, l1);
            *(uint2*)(bp + row * A_ST + aSeg * 8)         = make_uint2(h0, h1);
            *(uint2*)(bp + ATILE + row * A_ST + aSeg * 8) = make_uint2(l0, l1);
            const int kr = bKr + i * 8;
            split2(pb[i].x, pb[i].y, h0, l0);
            split2(pb[i].z, pb[i].w, h1, l1);
            *(uint2*)(bp + B_OFF + kr * B_ST + bNs * 8)         = make_uint2(h0, h1);
            *(uint2*)(bp + B_OFF + BTILE + kr * B_ST + bNs * 8) = make_uint2(l0, l1);
        }
    };

    // prologue: buf0 filled; regs hold chunk 1
    gload(0);
    sstore(0);
    if (NC > 1) gload(1);
    __syncthreads();

#pragma unroll 1
    for (int c = 0; c < NC; c++) {
        const uint32_t bb = sb + (c & 1) * BUFSZ;

        // A fragments (row-major, non-trans ldmatrix), mapping verified in R13
        uint32_t ah[2][4], al[2][4];
#pragma unroll
        for (int mf = 0; mf < 2; mf++) {
            const uint32_t ao = bb
                + (uint32_t)(warp_m * 32 + mf * 16 + (lane & 15)) * A_ST
                + (uint32_t)(lane >> 4) * 16;
            ldmx4(ah[mf], ao);
            ldmx4(al[mf], ao + ATILE);
        }

        // Overlapped with MMA issue below: store chunk c+1 into the OTHER buffer,
        // then refill regs with chunk c+2. Legal: buf(c+1) readers finished at the
        // end-of-iteration barrier of iter c-1; buf(c) stores completed there too.
        if (c + 1 < NC) sstore(c + 1);
        if (c + 2 < NC) gload(c + 2);

        // B fragments + MMAs; accumulator round-robin gives RAW distance 4.
        const int q = lane >> 3;
#pragma unroll
        for (int np = 0; np < 4; np++) {
            const uint32_t bo = bb + B_OFF
                + (uint32_t)((q & 1) * 8 + (lane & 7)) * B_ST
                + (uint32_t)(warp_n * 64 + np * 16 + (q >> 1) * 8) * 2;
            uint32_t t[4], u[4];
            ldmx4t(t, bo);           // bh pair for nf = 2np, 2np+1
            ldmx4t(u, bo + BTILE);   // bl pair
            mma16816(acc[0][2 * np],     ah[0], &t[0]);
            mma16816(acc[0][2 * np + 1], ah[0], &t[2]);
            mma16816(acc[1][2 * np],     ah[1], &t[0]);
            mma16816(acc[1][2 * np + 1], ah[1], &t[2]);
            mma16816(acc[0][2 * np],     al[0], &t[0]);
            mma16816(acc[0][2 * np + 1], al[0], &t[2]);
            mma16816(acc[1][2 * np],     al[1], &t[0]);
            mma16816(acc[1][2 * np + 1], al[1], &t[2]);
            mma16816(acc[0][2 * np],     ah[0], &u[0]);
            mma16816(acc[0][2 * np + 1], ah[0], &u[2]);
            mma16816(acc[1][2 * np],     ah[1], &u[0]);
            mma16816(acc[1][2 * np + 1], ah[1], &u[2]);
        }
        __syncthreads();   // buf(c+1) ready; all warps done reading buf(c)
    }

    // ---- epilogue (fp32 out; relu for layer 1) ----
    float* __restrict__ C =
        (float*)(WHICH ? (void*)g_eout4 : (void*)g_hid4) + (size_t)e * ROWS_PER_E * NDIM;
    const int er0 = m0 + warp_m * 32 + (lane >> 2);
    const int ec0 = n0 + warp_n * 64 + 2 * (lane & 3);
#pragma unroll
    for (int mf = 0; mf < 2; mf++) {
#pragma unroll
        for (int nf = 0; nf < 8; nf++) {
#pragma unroll
            for (int half = 0; half < 2; half++) {
                const int rr = er0 + mf * 16 + half * 8;
                const int cc = ec0 + nf * 8;
                float v0 = acc[mf][nf][2 * half];
                float v1 = acc[mf][nf][2 * half + 1];
                if (WHICH == 0) { v0 = fmaxf(v0, 0.f); v1 = fmaxf(v1, 0.f); }
                *(float2*)(C + (size_t)rr * NDIM + cc) = make_float2(v0, v1);
            }
        }
    }
}

// ---------------- 5) combine (identical to R13 pass) ----------------
__global__ void combine_kernel(float4* __restrict__ out4)
{
    const int warp = threadIdx.x >> 5, lane = threadIdx.x & 31;
    const int tok = blockIdx.x * 8 + warp;
    const int b = tok >> 12;
    const int s1v = g_s1[tok], s2v = g_s2[tok];
    const float g1 = g_g1[tok], g2 = g_g2[tok];
    const bool h1 = s1v >= 0, h2 = s2v >= 0;
    const float4* p1 = g_eout4 + (((size_t)g_i1[tok] * 2 + b) * CAP + (h1 ? s1v : 0)) * (D / 4);
    const float4* p2 = g_eout4 + (((size_t)g_i2[tok] * 2 + b) * CAP + (h2 ? s2v : 0)) * (D / 4);
    float4* op = out4 + (size_t)tok * (D / 4);
#pragma unroll
    for (int i = lane; i < D / 4; i += 32) {
        float4 r = make_float4(0.f, 0.f, 0.f, 0.f);
        if (h1) { const float4 a = p1[i]; r.x = fmaf(g1, a.x, r.x); r.y = fmaf(g1, a.y, r.y);
                  r.z = fmaf(g1, a.z, r.z); r.w = fmaf(g1, a.w, r.w); }
        if (h2) { const float4 a = p2[i]; r.x = fmaf(g2, a.x, r.x); r.y = fmaf(g2, a.y, r.y);
                  r.z = fmaf(g2, a.z, r.z); r.w = fmaf(g2, a.w, r.w); }
        op[i] = r;
    }
}

// ---------------- launcher ----------------
extern "C" void kernel_launch(void* const* d_in, const int* in_sizes, int n_in,
                              void* d_out, int out_size)
{
    const float* x  = (const float*)d_in[0];   // [2,4096,512]
    const float* wg = (const float*)d_in[1];   // [512,16]
    const float* w1 = (const float*)d_in[2];   // [16,512,2048]
    const float* w2 = (const float*)d_in[3];   // [16,2048,512]
    float4* out = (float4*)d_out;              // [2,4096,512]

    gating_kernel<<<N_TOK / 8, 256>>>(x, wg);
    schedule_kernel<<<2, 512>>>();
    gather_kernel<<<16384 / 8, 256>>>((const float4*)x);

    hmma_ffn_kernel<D, H, 0><<<dim3(H / 128, ROWS_PER_E / 128, E), 256>>>(w1);
    hmma_ffn_kernel<H, D, 1><<<dim3(D / 128, ROWS_PER_E / 128, E), 256>>>(w2);

    combine_kernel<<<N_TOK / 8, 256>>>(out);
}